// round 14
// baseline (speedup 1.0000x reference)
#include <cuda_runtime.h>
#include <cuda_fp16.h>
#include <cstdint>

#define NN 200000
#define NE 1600000
#define NG 2000
#define DD 64
#define NVOC 10000
#define NBLK 196        // ceil(NN/1024)
#define EMBB 313        // embW blocks (32 rows each)
#define CNTB 1563       // count blocks (1024 edges each, 4/thread)
#define FILLB 1563      // fill blocks in k_post
#define SEEDB 6250      // seed blocks in k_post (NN*8/256)

// ---------------- scratch (static device globals; no allocations) ----------
__device__ int     g_deg[NN];
__device__ int     g_off[NN];
__device__ int     g_cur[NN];
__device__ float   g_dinv[NN];
__device__ int     g_csr[NE];
__device__ int     g_alloc;
__device__ __align__(16) __half2 g_embWh[NVOC * 32];  // fp16(emb@W1), 1.25MB
__device__ __align__(16) __half2 g_T1h[NN * 32];      // fp16(dinv*embW[x])
__device__ __align__(16) __half2 g_T2h[NN * 32];      // fp16(dinv*(h1@W2))
__device__ __align__(4)  __half  g_W2th[DD * DD];     // fp16 W2 transposed [n][k]
__device__ float   g_gsum[NG * DD];
__device__ float   g_cnt[NG];

// ---------------- mma helpers ------------------------------------------------
__device__ __forceinline__ void mma16816(float& c0, float& c1, float& c2, float& c3,
                                         uint32_t a0, uint32_t a1, uint32_t a2, uint32_t a3,
                                         uint32_t b0, uint32_t b1) {
    asm volatile("mma.sync.aligned.m16n8k16.row.col.f32.f16.f16.f32 "
                 "{%0,%1,%2,%3},{%4,%5,%6,%7},{%8,%9},{%0,%1,%2,%3};"
                 : "+f"(c0), "+f"(c1), "+f"(c2), "+f"(c3)
                 : "r"(a0), "r"(a1), "r"(a2), "r"(a3), "r"(b0), "r"(b1));
}
__device__ __forceinline__ void ldsm4(uint32_t& a0, uint32_t& a1, uint32_t& a2, uint32_t& a3,
                                      uint32_t addr) {
    asm volatile("ldmatrix.sync.aligned.m8n8.x4.shared.b16 {%0,%1,%2,%3},[%4];"
                 : "=r"(a0), "=r"(a1), "=r"(a2), "=r"(a3) : "r"(addr));
}

// ---------------- fused: embW GEMM + degree count (REDG) + W2 fp16 ----------
__global__ void k_prep(const float* __restrict__ emb,
                       const float* __restrict__ W,
                       const float* __restrict__ W2,
                       const int* __restrict__ ei) {
    __shared__ __align__(16) float Ws[64 * 64];
    __shared__ __align__(16) float As[32][68];
    int tid = threadIdx.x;           // 256 threads
    if (blockIdx.x >= EMBB) {
        // ---- degree count path (result unused -> REDG, fast) ----
        int t = (blockIdx.x - EMBB) * 256 + tid;
        if (t == 0) g_alloc = 0;
        if (t < NG * DD) g_gsum[t] = 0.f;
        if (t < NG) g_cnt[t] = 0.f;
        if (blockIdx.x == EMBB) {
            // transpose-convert W2 -> fp16 [n][k]
#pragma unroll
            for (int j = 0; j < 16; j++) {
                int e = j * 256 + tid;          // e = n*64 + k
                int n = e >> 6, k = e & 63;
                g_W2th[e] = __float2half(W2[k * 64 + n]);
            }
        }
        int e = t * 4;
        if (e < NE) {
            int4 d4 = *(const int4*)&ei[NE + e];
            atomicAdd(&g_deg[d4.x], 1);
            atomicAdd(&g_deg[d4.y], 1);
            atomicAdd(&g_deg[d4.z], 1);
            atomicAdd(&g_deg[d4.w], 1);
        }
        return;
    }
    // ---- embW path ----
    for (int i = tid; i < 4096; i += 256) Ws[i] = W[i];
    int rowbase = blockIdx.x * 32;
#pragma unroll
    for (int q = 0; q < 2; q++) {
        int lin4 = q * 256 + tid;
        int r = lin4 >> 4;
        int cc = (lin4 & 15) << 2;
        int v = rowbase + r;
        float4 val = make_float4(0.f, 0.f, 0.f, 0.f);
        if (v < NVOC) val = *(const float4*)&emb[v * 64 + cc];
        *(float4*)&As[r][cc] = val;
    }
    __syncthreads();

    int tx = tid & 15, ty = tid >> 4;
    float acc[2][4] = {};
#pragma unroll
    for (int k = 0; k < 64; k++) {
        float4 bv = *(const float4*)&Ws[k * 64 + tx * 4];
#pragma unroll
        for (int r = 0; r < 2; r++) {
            float a = As[ty * 2 + r][k];
            acc[r][0] = fmaf(a, bv.x, acc[r][0]);
            acc[r][1] = fmaf(a, bv.y, acc[r][1]);
            acc[r][2] = fmaf(a, bv.z, acc[r][2]);
            acc[r][3] = fmaf(a, bv.w, acc[r][3]);
        }
    }
#pragma unroll
    for (int r = 0; r < 2; r++) {
        int v = rowbase + ty * 2 + r;
        if (v < NVOC) {
            g_embWh[v * 32 + tx * 2]     = __floats2half2_rn(acc[r][0], acc[r][1]);
            g_embWh[v * 32 + tx * 2 + 1] = __floats2half2_rn(acc[r][2], acc[r][3]);
        }
    }
}

// ---------------- one-pass scan: disjoint CSR segments (order-free) --------
__global__ void k_scan() {
    int tid = threadIdx.x;
    int lane = tid & 31, wid = tid >> 5;
    int i = blockIdx.x * 1024 + tid;
    int v = (i < NN) ? g_deg[i] : 0;

    int xv = v;
#pragma unroll
    for (int d = 1; d < 32; d <<= 1) {
        int t = __shfl_up_sync(0xffffffffu, xv, d);
        if (lane >= d) xv += t;
    }
    __shared__ int wsum[32];
    if (lane == 31) wsum[wid] = xv;
    __syncthreads();
    if (tid < 32) {
        int y = wsum[tid];
#pragma unroll
        for (int d = 1; d < 32; d <<= 1) {
            int t = __shfl_up_sync(0xffffffffu, y, d);
            if (tid >= d) y += t;
        }
        wsum[tid] = y;
    }
    __syncthreads();
    int incl = xv + (wid > 0 ? wsum[wid - 1] : 0);

    __shared__ int sbase;
    if (tid == 1023) sbase = atomicAdd(&g_alloc, incl);
    __syncthreads();

    if (i < NN) {
        int excl = sbase + incl - v;
        g_off[i] = excl;
        g_cur[i] = excl;
        g_dinv[i] = rsqrtf((float)(v + 1));
    }
}

// ---------------- fused: csr fill (atomic) + T1 seed -------------------------
__global__ void k_post(const int* __restrict__ ei, const int* __restrict__ x) {
    int tid = threadIdx.x;           // 256 threads
    if (blockIdx.x < FILLB) {
        // ---- fill path ----
        int e = (blockIdx.x * 256 + tid) * 4;
        if (e < NE) {
            int4 d4 = *(const int4*)&ei[NE + e];
            int4 s4 = *(const int4*)&ei[e];
            int p0 = atomicAdd(&g_cur[d4.x], 1);
            int p1 = atomicAdd(&g_cur[d4.y], 1);
            int p2 = atomicAdd(&g_cur[d4.z], 1);
            int p3 = atomicAdd(&g_cur[d4.w], 1);
            g_csr[p0] = s4.x;
            g_csr[p1] = s4.y;
            g_csr[p2] = s4.z;
            g_csr[p3] = s4.w;
        }
        return;
    }
    // ---- seed path: T1[v] = fp16(dinv[v] * embWh[x[v]]) ----
    int t = (blockIdx.x - FILLB) * 256 + tid;    // one uint4 per thread
    if (t >= NN * 8) return;
    int v = t >> 3, li = t & 7;
    int tok = __ldg(&x[v]);
    float dv = g_dinv[v];
    uint4 u = __ldg(&((const uint4*)g_embWh)[tok * 8 + li]);
    __half2* h = (__half2*)&u;
#pragma unroll
    for (int k = 0; k < 4; k++) {
        float2 f = __half22float2(h[k]);
        h[k] = __floats2half2_rn(f.x * dv, f.y * dv);
    }
    ((uint4*)g_T1h)[t] = u;
}

// ---- shared gather core: fp16 accumulation, L2-only row loads (__ldcg) -----
// 4 nodes/warp (groups of 8 lanes), cooperative csr loads + shfl broadcast.
// (R9 memory schedule — measured good; do not "pipeline" this loop.)
__device__ __forceinline__ void gather_rows_h(const uint4* __restrict__ tv,
                                              const int* __restrict__ cs,
                                              int dg, int dgmax, int li,
                                              __half2* acc) {
#pragma unroll 1
    for (int i = 0; i < dgmax; i += 8) {
        int s = (i + li < dg) ? __ldg(&cs[i + li]) : -1;
#pragma unroll
        for (int j = 0; j < 8; j++) {
            int sj = __shfl_sync(0xffffffffu, s, j, 8);
            if (sj >= 0) {
                uint4 u = __ldcg(&tv[sj * 8 + li]);   // L2-only: no L1 reuse
                acc[0] = __hadd2(acc[0], *(__half2*)&u.x);
                acc[1] = __hadd2(acc[1], *(__half2*)&u.y);
                acc[2] = __hadd2(acc[2], *(__half2*)&u.z);
                acc[3] = __hadd2(acc[3], *(__half2*)&u.w);
            }
        }
    }
}

// ---------------- layer1 gather (T1) + layer2 GEMM via HMMA -----------------
__global__ void __launch_bounds__(256, 4)
k_gather_gemm(const float* __restrict__ b1) {
    __shared__ __align__(16) __half As[64][72];   // h1 tile, fp16, padded
    int tid = threadIdx.x;           // 256 threads
    int w = tid >> 5, l = tid & 31;
    int q = l >> 3, li = l & 7;
    int base = blockIdx.x * 64;
    float4 bb0 = __ldg(&((const float4*)b1)[li * 2]);
    float4 bb1 = __ldg(&((const float4*)b1)[li * 2 + 1]);
    const uint4* tv = (const uint4*)g_T1h;

    int offp = 0, degp = 0;
    float dvp = 0.f;
    if (l < 8) {
        int nv = base + (w << 3) + l;
        offp = g_off[nv];
        degp = g_deg[nv];
        dvp  = g_dinv[nv];
    }
#pragma unroll
    for (int it = 0; it < 2; it++) {
        int na  = it * 4 + q;
        int v   = base + (w << 3) + na;
        int off = __shfl_sync(0xffffffffu, offp, na);
        int dg  = __shfl_sync(0xffffffffu, degp, na);
        float dv = __shfl_sync(0xffffffffu, dvp, na);
        int d0 = __shfl_sync(0xffffffffu, degp, it * 4);
        int d1 = __shfl_sync(0xffffffffu, degp, it * 4 + 1);
        int d2 = __shfl_sync(0xffffffffu, degp, it * 4 + 2);
        int d3 = __shfl_sync(0xffffffffu, degp, it * 4 + 3);
        int dgmax = max(max(d0, d1), max(d2, d3));

        uint4 se = __ldcg(&tv[v * 8 + li]);   // self loop (L2-only)
        __half2 acc[4];
        acc[0] = *(__half2*)&se.x;
        acc[1] = *(__half2*)&se.y;
        acc[2] = *(__half2*)&se.z;
        acc[3] = *(__half2*)&se.w;
        gather_rows_h(tv, g_csr + off, dg, dgmax, li, acc);

        float2 f0 = __half22float2(acc[0]);
        float2 f1 = __half22float2(acc[1]);
        float2 f2 = __half22float2(acc[2]);
        float2 f3 = __half22float2(acc[3]);
        // relu(dinv*acc + b) -> fp16 smem
        __half2 h01 = __floats2half2_rn(fmaxf(fmaf(dv, f0.x, bb0.x), 0.f),
                                        fmaxf(fmaf(dv, f0.y, bb0.y), 0.f));
        __half2 h23 = __floats2half2_rn(fmaxf(fmaf(dv, f1.x, bb0.z), 0.f),
                                        fmaxf(fmaf(dv, f1.y, bb0.w), 0.f));
        __half2 h45 = __floats2half2_rn(fmaxf(fmaf(dv, f2.x, bb1.x), 0.f),
                                        fmaxf(fmaf(dv, f2.y, bb1.y), 0.f));
        __half2 h67 = __floats2half2_rn(fmaxf(fmaf(dv, f3.x, bb1.z), 0.f),
                                        fmaxf(fmaf(dv, f3.y, bb1.w), 0.f));
        int row = (w << 3) + na;
        __half2* dst = (__half2*)&As[row][li * 8];
        dst[0] = h01; dst[1] = h23; dst[2] = h45; dst[3] = h67;
    }
    __syncthreads();

    // ---- HMMA: T2 = fp16(dinv * (As @ W2)) ----
    int mbase = (w & 3) * 16;
    int nhalf = w >> 2;
    const uint32_t* Bw = (const uint32_t*)g_W2th;   // [n][k] fp16 pairs

    float acc[4][4] = {};
#pragma unroll
    for (int kk = 0; kk < 4; kk++) {
        uint32_t a0, a1, a2, a3;
        uint32_t sa = (uint32_t)__cvta_generic_to_shared(
            &As[mbase + (l & 15)][kk * 16 + (l >> 4) * 8]);
        ldsm4(a0, a1, a2, a3, sa);
#pragma unroll
        for (int t = 0; t < 4; t++) {
            int n = nhalf * 32 + t * 8 + (l >> 2);
            uint32_t b0 = __ldg(&Bw[n * 32 + kk * 8 + (l & 3)]);
            uint32_t b1 = __ldg(&Bw[n * 32 + kk * 8 + 4 + (l & 3)]);
            mma16816(acc[t][0], acc[t][1], acc[t][2], acc[t][3],
                     a0, a1, a2, a3, b0, b1);
        }
    }
    int r0 = mbase + (l >> 2);
    int r1 = r0 + 8;
    float dv0 = g_dinv[base + r0];
    float dv1 = g_dinv[base + r1];
#pragma unroll
    for (int t = 0; t < 4; t++) {
        int cidx = nhalf * 16 + t * 4 + (l & 3);
        g_T2h[(base + r0) * 32 + cidx] =
            __floats2half2_rn(acc[t][0] * dv0, acc[t][1] * dv0);
        g_T2h[(base + r1) * 32 + cidx] =
            __floats2half2_rn(acc[t][2] * dv1, acc[t][3] * dv1);
    }
}

// ---------------- layer2 gather + mean-pool fused ---------------------------
__global__ void __launch_bounds__(256, 4)
k_gather_pool(const float* __restrict__ b2,
              const int* __restrict__ batch) {
    __shared__ __align__(16) float As[64][68];
    __shared__ int sb[64];
    int tid = threadIdx.x;           // 256 threads
    int w = tid >> 5, l = tid & 31;
    int q = l >> 3, li = l & 7;
    int base = blockIdx.x * 64;
    if (tid < 64) sb[tid] = __ldg(&batch[base + tid]);
    float4 bb0 = __ldg(&((const float4*)b2)[li * 2]);
    float4 bb1 = __ldg(&((const float4*)b2)[li * 2 + 1]);
    const uint4* tv = (const uint4*)g_T2h;

    int offp = 0, degp = 0;
    float dvp = 0.f;
    if (l < 8) {
        int nv = base + (w << 3) + l;
        offp = g_off[nv];
        degp = g_deg[nv];
        dvp  = g_dinv[nv];
    }
#pragma unroll
    for (int it = 0; it < 2; it++) {
        int na  = it * 4 + q;
        int v   = base + (w << 3) + na;
        int off = __shfl_sync(0xffffffffu, offp, na);
        int dg  = __shfl_sync(0xffffffffu, degp, na);
        float dv = __shfl_sync(0xffffffffu, dvp, na);
        int d0 = __shfl_sync(0xffffffffu, degp, it * 4);
        int d1 = __shfl_sync(0xffffffffu, degp, it * 4 + 1);
        int d2 = __shfl_sync(0xffffffffu, degp, it * 4 + 2);
        int d3 = __shfl_sync(0xffffffffu, degp, it * 4 + 3);
        int dgmax = max(max(d0, d1), max(d2, d3));

        uint4 se = __ldcg(&tv[v * 8 + li]);     // self loop (L2-only)
        __half2 acc[4];
        acc[0] = *(__half2*)&se.x;
        acc[1] = *(__half2*)&se.y;
        acc[2] = *(__half2*)&se.z;
        acc[3] = *(__half2*)&se.w;
        gather_rows_h(tv, g_csr + off, dg, dgmax, li, acc);

        float2 f0 = __half22float2(acc[0]);
        float2 f1 = __half22float2(acc[1]);
        float2 f2 = __half22float2(acc[2]);
        float2 f3 = __half22float2(acc[3]);
        float o[8];
        o[0] = fmaxf(fmaf(dv, f0.x, bb0.x), 0.f);
        o[1] = fmaxf(fmaf(dv, f0.y, bb0.y), 0.f);
        o[2] = fmaxf(fmaf(dv, f1.x, bb0.z), 0.f);
        o[3] = fmaxf(fmaf(dv, f1.y, bb0.w), 0.f);
        o[4] = fmaxf(fmaf(dv, f2.x, bb1.x), 0.f);
        o[5] = fmaxf(fmaf(dv, f2.y, bb1.y), 0.f);
        o[6] = fmaxf(fmaf(dv, f3.x, bb1.z), 0.f);
        o[7] = fmaxf(fmaf(dv, f3.y, bb1.w), 0.f);
        int row = (w << 3) + na;
        *(float4*)&As[row][li * 8]     = make_float4(o[0], o[1], o[2], o[3]);
        *(float4*)&As[row][li * 8 + 4] = make_float4(o[4], o[5], o[6], o[7]);
    }
    __syncthreads();

    // 64 threads: run-length pool over the 64 smem rows (batch is sorted)
    if (tid < 64) {
        int j = tid;
        int cur = sb[0];
        float acc = 0.f;
        int run = 0;
#pragma unroll 1
        for (int n = 0; n < 64; n++) {
            int gv = sb[n];
            if (gv != cur) {
                atomicAdd(&g_gsum[cur * 64 + j], acc);
                if (j == 0) atomicAdd(&g_cnt[cur], (float)run);
                acc = 0.f;
                run = 0;
                cur = gv;
            }
            acc += As[n][j];
            run++;
        }
        atomicAdd(&g_gsum[cur * 64 + j], acc);
        if (j == 0) atomicAdd(&g_cnt[cur], (float)run);
    }
}

// ---------------- classifier head ------------------------------------------
__global__ void k_final(const float* __restrict__ Wlin,
                        const float* __restrict__ blin,
                        float* __restrict__ out) {
    int g = blockIdx.x * blockDim.x + threadIdx.x;
    if (g >= NG) return;
    float inv = 1.0f / fmaxf(g_cnt[g], 1.0f);
    float a0 = blin[0], a1 = blin[1];
#pragma unroll 8
    for (int j = 0; j < 64; j++) {
        float m = g_gsum[g * 64 + j] * inv;
        a0 = fmaf(m, Wlin[2 * j], a0);
        a1 = fmaf(m, Wlin[2 * j + 1], a1);
    }
    out[2 * g] = a0;
    out[2 * g + 1] = a1;
}

// ---------------- launch ----------------------------------------------------
extern "C" void kernel_launch(void* const* d_in, const int* in_sizes, int n_in,
                              void* d_out, int out_size) {
    const int* x      = (const int*)d_in[0];
    const int* ei     = (const int*)d_in[1];   // [2, NE] row-major
    // d_in[2] = edge_type (unused by GCNConv)
    const int* batch  = (const int*)d_in[3];
    const float* emb  = (const float*)d_in[4];
    const float* W1   = (const float*)d_in[5];
    const float* b1   = (const float*)d_in[6];
    const float* W2   = (const float*)d_in[7];
    const float* b2   = (const float*)d_in[8];
    const float* Wlin = (const float*)d_in[9];
    const float* blin = (const float*)d_in[10];
    float* out = (float*)d_out;

    void* degp = nullptr;
    cudaGetSymbolAddress(&degp, g_deg);
    cudaMemsetAsync(degp, 0, NN * sizeof(int));

    k_prep<<<EMBB + CNTB, 256>>>(emb, W1, W2, ei);   // embW + count + W2->fp16
    k_scan<<<NBLK, 1024>>>();
    k_post<<<FILLB + SEEDB, 256>>>(ei, x);           // csr fill + T1 seed

    k_gather_gemm<<<NN / 64, 256>>>(b1);
    k_gather_pool<<<NN / 64, 256>>>(b2, batch);

    k_final<<<(NG + 255) / 256, 256>>>(Wlin, blin, out);
}

// round 15
// speedup vs baseline: 1.0534x; 1.0534x over previous
#include <cuda_runtime.h>
#include <cuda_fp16.h>
#include <cstdint>

#define NN 200000
#define NE 1600000
#define NG 2000
#define DD 64
#define NVOC 10000
#define NBLK 196        // ceil(NN/1024)
#define EMBB 313        // embW blocks (32 rows each)
#define CNTB 1563       // count blocks (1024 edges each, 4/thread)
#define FILLB 1563      // fill blocks in k_post
#define SEEDB 6250      // seed blocks in k_post (NN*8/256)

// ---------------- scratch (static device globals; no allocations) ----------
__device__ int     g_deg[NN];
__device__ int     g_off[NN];
__device__ int     g_cur[NN];
__device__ float   g_dinv[NN];
__device__ int     g_csr[NE];
__device__ int     g_alloc;
__device__ __align__(16) __half2 g_embWh[NVOC * 32];  // fp16(emb@W1), 1.25MB
__device__ __align__(16) __half2 g_T1h[NN * 32];      // fp16(dinv*embW[x])
__device__ __align__(16) __half2 g_T2h[NN * 32];      // fp16(dinv*(h1@W2))
__device__ __align__(4)  __half  g_W2th[DD * DD];     // fp16 W2 transposed [n][k]
__device__ float   g_gsum[NG * DD];
__device__ float   g_cnt[NG];

// ---------------- mma helpers ------------------------------------------------
__device__ __forceinline__ void mma16816(float& c0, float& c1, float& c2, float& c3,
                                         uint32_t a0, uint32_t a1, uint32_t a2, uint32_t a3,
                                         uint32_t b0, uint32_t b1) {
    asm volatile("mma.sync.aligned.m16n8k16.row.col.f32.f16.f16.f32 "
                 "{%0,%1,%2,%3},{%4,%5,%6,%7},{%8,%9},{%0,%1,%2,%3};"
                 : "+f"(c0), "+f"(c1), "+f"(c2), "+f"(c3)
                 : "r"(a0), "r"(a1), "r"(a2), "r"(a3), "r"(b0), "r"(b1));
}
__device__ __forceinline__ void ldsm4(uint32_t& a0, uint32_t& a1, uint32_t& a2, uint32_t& a3,
                                      uint32_t addr) {
    asm volatile("ldmatrix.sync.aligned.m8n8.x4.shared.b16 {%0,%1,%2,%3},[%4];"
                 : "=r"(a0), "=r"(a1), "=r"(a2), "=r"(a3) : "r"(addr));
}

// ---------------- fused: embW GEMM + degree count (REDG) + W2 fp16 ----------
__global__ void k_prep(const float* __restrict__ emb,
                       const float* __restrict__ W,
                       const float* __restrict__ W2,
                       const int* __restrict__ ei) {
    __shared__ __align__(16) float Ws[64 * 64];
    __shared__ __align__(16) float As[32][68];
    int tid = threadIdx.x;           // 256 threads
    if (blockIdx.x >= EMBB) {
        // ---- degree count path (result unused -> REDG, fast) ----
        int t = (blockIdx.x - EMBB) * 256 + tid;
        if (t == 0) g_alloc = 0;
        if (t < NG * DD) g_gsum[t] = 0.f;
        if (t < NG) g_cnt[t] = 0.f;
        if (blockIdx.x == EMBB) {
            // transpose-convert W2 -> fp16 [n][k]
#pragma unroll
            for (int j = 0; j < 16; j++) {
                int e = j * 256 + tid;          // e = n*64 + k
                int n = e >> 6, k = e & 63;
                g_W2th[e] = __float2half(W2[k * 64 + n]);
            }
        }
        int e = t * 4;
        if (e < NE) {
            int4 d4 = *(const int4*)&ei[NE + e];
            atomicAdd(&g_deg[d4.x], 1);
            atomicAdd(&g_deg[d4.y], 1);
            atomicAdd(&g_deg[d4.z], 1);
            atomicAdd(&g_deg[d4.w], 1);
        }
        return;
    }
    // ---- embW path ----
    for (int i = tid; i < 4096; i += 256) Ws[i] = W[i];
    int rowbase = blockIdx.x * 32;
#pragma unroll
    for (int q = 0; q < 2; q++) {
        int lin4 = q * 256 + tid;
        int r = lin4 >> 4;
        int cc = (lin4 & 15) << 2;
        int v = rowbase + r;
        float4 val = make_float4(0.f, 0.f, 0.f, 0.f);
        if (v < NVOC) val = *(const float4*)&emb[v * 64 + cc];
        *(float4*)&As[r][cc] = val;
    }
    __syncthreads();

    int tx = tid & 15, ty = tid >> 4;
    float acc[2][4] = {};
#pragma unroll
    for (int k = 0; k < 64; k++) {
        float4 bv = *(const float4*)&Ws[k * 64 + tx * 4];
#pragma unroll
        for (int r = 0; r < 2; r++) {
            float a = As[ty * 2 + r][k];
            acc[r][0] = fmaf(a, bv.x, acc[r][0]);
            acc[r][1] = fmaf(a, bv.y, acc[r][1]);
            acc[r][2] = fmaf(a, bv.z, acc[r][2]);
            acc[r][3] = fmaf(a, bv.w, acc[r][3]);
        }
    }
#pragma unroll
    for (int r = 0; r < 2; r++) {
        int v = rowbase + ty * 2 + r;
        if (v < NVOC) {
            g_embWh[v * 32 + tx * 2]     = __floats2half2_rn(acc[r][0], acc[r][1]);
            g_embWh[v * 32 + tx * 2 + 1] = __floats2half2_rn(acc[r][2], acc[r][3]);
        }
    }
}

// ---------------- one-pass scan: disjoint CSR segments (order-free) --------
__global__ void k_scan() {
    int tid = threadIdx.x;
    int lane = tid & 31, wid = tid >> 5;
    int i = blockIdx.x * 1024 + tid;
    int v = (i < NN) ? g_deg[i] : 0;

    int xv = v;
#pragma unroll
    for (int d = 1; d < 32; d <<= 1) {
        int t = __shfl_up_sync(0xffffffffu, xv, d);
        if (lane >= d) xv += t;
    }
    __shared__ int wsum[32];
    if (lane == 31) wsum[wid] = xv;
    __syncthreads();
    if (tid < 32) {
        int y = wsum[tid];
#pragma unroll
        for (int d = 1; d < 32; d <<= 1) {
            int t = __shfl_up_sync(0xffffffffu, y, d);
            if (tid >= d) y += t;
        }
        wsum[tid] = y;
    }
    __syncthreads();
    int incl = xv + (wid > 0 ? wsum[wid - 1] : 0);

    __shared__ int sbase;
    if (tid == 1023) sbase = atomicAdd(&g_alloc, incl);
    __syncthreads();

    if (i < NN) {
        int excl = sbase + incl - v;
        g_off[i] = excl;
        g_cur[i] = excl;
        g_dinv[i] = rsqrtf((float)(v + 1));
    }
}

// ---------------- fused: csr fill (atomic) + T1 seed -------------------------
__global__ void k_post(const int* __restrict__ ei, const int* __restrict__ x) {
    int tid = threadIdx.x;           // 256 threads
    if (blockIdx.x < FILLB) {
        // ---- fill path ----
        int e = (blockIdx.x * 256 + tid) * 4;
        if (e < NE) {
            int4 d4 = *(const int4*)&ei[NE + e];
            int4 s4 = *(const int4*)&ei[e];
            int p0 = atomicAdd(&g_cur[d4.x], 1);
            int p1 = atomicAdd(&g_cur[d4.y], 1);
            int p2 = atomicAdd(&g_cur[d4.z], 1);
            int p3 = atomicAdd(&g_cur[d4.w], 1);
            g_csr[p0] = s4.x;
            g_csr[p1] = s4.y;
            g_csr[p2] = s4.z;
            g_csr[p3] = s4.w;
        }
        return;
    }
    // ---- seed path: T1[v] = fp16(dinv[v] * embWh[x[v]]) ----
    int t = (blockIdx.x - FILLB) * 256 + tid;    // one uint4 per thread
    if (t >= NN * 8) return;
    int v = t >> 3, li = t & 7;
    int tok = __ldg(&x[v]);
    float dv = g_dinv[v];
    uint4 u = __ldg(&((const uint4*)g_embWh)[tok * 8 + li]);
    __half2* h = (__half2*)&u;
#pragma unroll
    for (int k = 0; k < 4; k++) {
        float2 f = __half22float2(h[k]);
        h[k] = __floats2half2_rn(f.x * dv, f.y * dv);
    }
    ((uint4*)g_T1h)[t] = u;
}

// ---- shared gather core: fp16 accumulation, L2-only row loads (__ldcg) -----
// 4 nodes/warp (groups of 8 lanes), cooperative csr loads + shfl broadcast.
// (R9 memory schedule — measured good; do not "pipeline" this loop.)
__device__ __forceinline__ void gather_rows_h(const uint4* __restrict__ tv,
                                              const int* __restrict__ cs,
                                              int dg, int dgmax, int li,
                                              __half2* acc) {
#pragma unroll 1
    for (int i = 0; i < dgmax; i += 8) {
        int s = (i + li < dg) ? __ldg(&cs[i + li]) : -1;
#pragma unroll
        for (int j = 0; j < 8; j++) {
            int sj = __shfl_sync(0xffffffffu, s, j, 8);
            if (sj >= 0) {
                uint4 u = __ldcg(&tv[sj * 8 + li]);   // L2-only: no L1 reuse
                acc[0] = __hadd2(acc[0], *(__half2*)&u.x);
                acc[1] = __hadd2(acc[1], *(__half2*)&u.y);
                acc[2] = __hadd2(acc[2], *(__half2*)&u.z);
                acc[3] = __hadd2(acc[3], *(__half2*)&u.w);
            }
        }
    }
}

// ---------------- layer1 gather (T1) + layer2 GEMM via HMMA -----------------
__global__ void k_gather_gemm(const float* __restrict__ b1) {
    __shared__ __align__(16) __half As[64][72];   // h1 tile, fp16, padded
    int tid = threadIdx.x;           // 256 threads
    int w = tid >> 5, l = tid & 31;
    int q = l >> 3, li = l & 7;
    int base = blockIdx.x * 64;
    float4 bb0 = __ldg(&((const float4*)b1)[li * 2]);
    float4 bb1 = __ldg(&((const float4*)b1)[li * 2 + 1]);
    const uint4* tv = (const uint4*)g_T1h;

    int offp = 0, degp = 0;
    float dvp = 0.f;
    if (l < 8) {
        int nv = base + (w << 3) + l;
        offp = g_off[nv];
        degp = g_deg[nv];
        dvp  = g_dinv[nv];
    }
#pragma unroll
    for (int it = 0; it < 2; it++) {
        int na  = it * 4 + q;
        int v   = base + (w << 3) + na;
        int off = __shfl_sync(0xffffffffu, offp, na);
        int dg  = __shfl_sync(0xffffffffu, degp, na);
        float dv = __shfl_sync(0xffffffffu, dvp, na);
        int d0 = __shfl_sync(0xffffffffu, degp, it * 4);
        int d1 = __shfl_sync(0xffffffffu, degp, it * 4 + 1);
        int d2 = __shfl_sync(0xffffffffu, degp, it * 4 + 2);
        int d3 = __shfl_sync(0xffffffffu, degp, it * 4 + 3);
        int dgmax = max(max(d0, d1), max(d2, d3));

        uint4 se = __ldcg(&tv[v * 8 + li]);   // self loop (L2-only)
        __half2 acc[4];
        acc[0] = *(__half2*)&se.x;
        acc[1] = *(__half2*)&se.y;
        acc[2] = *(__half2*)&se.z;
        acc[3] = *(__half2*)&se.w;
        gather_rows_h(tv, g_csr + off, dg, dgmax, li, acc);

        float2 f0 = __half22float2(acc[0]);
        float2 f1 = __half22float2(acc[1]);
        float2 f2 = __half22float2(acc[2]);
        float2 f3 = __half22float2(acc[3]);
        // relu(dinv*acc + b) -> fp16 smem
        __half2 h01 = __floats2half2_rn(fmaxf(fmaf(dv, f0.x, bb0.x), 0.f),
                                        fmaxf(fmaf(dv, f0.y, bb0.y), 0.f));
        __half2 h23 = __floats2half2_rn(fmaxf(fmaf(dv, f1.x, bb0.z), 0.f),
                                        fmaxf(fmaf(dv, f1.y, bb0.w), 0.f));
        __half2 h45 = __floats2half2_rn(fmaxf(fmaf(dv, f2.x, bb1.x), 0.f),
                                        fmaxf(fmaf(dv, f2.y, bb1.y), 0.f));
        __half2 h67 = __floats2half2_rn(fmaxf(fmaf(dv, f3.x, bb1.z), 0.f),
                                        fmaxf(fmaf(dv, f3.y, bb1.w), 0.f));
        int row = (w << 3) + na;
        __half2* dst = (__half2*)&As[row][li * 8];
        dst[0] = h01; dst[1] = h23; dst[2] = h45; dst[3] = h67;
    }
    __syncthreads();

    // ---- HMMA: T2 = fp16(dinv * (As @ W2)) ----
    int mbase = (w & 3) * 16;
    int nhalf = w >> 2;
    const uint32_t* Bw = (const uint32_t*)g_W2th;   // [n][k] fp16 pairs

    float acc[4][4] = {};
#pragma unroll
    for (int kk = 0; kk < 4; kk++) {
        uint32_t a0, a1, a2, a3;
        uint32_t sa = (uint32_t)__cvta_generic_to_shared(
            &As[mbase + (l & 15)][kk * 16 + (l >> 4) * 8]);
        ldsm4(a0, a1, a2, a3, sa);
#pragma unroll
        for (int t = 0; t < 4; t++) {
            int n = nhalf * 32 + t * 8 + (l >> 2);
            uint32_t b0 = __ldg(&Bw[n * 32 + kk * 8 + (l & 3)]);
            uint32_t b1 = __ldg(&Bw[n * 32 + kk * 8 + 4 + (l & 3)]);
            mma16816(acc[t][0], acc[t][1], acc[t][2], acc[t][3],
                     a0, a1, a2, a3, b0, b1);
        }
    }
    int r0 = mbase + (l >> 2);
    int r1 = r0 + 8;
    float dv0 = g_dinv[base + r0];
    float dv1 = g_dinv[base + r1];
#pragma unroll
    for (int t = 0; t < 4; t++) {
        int cidx = nhalf * 16 + t * 4 + (l & 3);
        g_T2h[(base + r0) * 32 + cidx] =
            __floats2half2_rn(acc[t][0] * dv0, acc[t][1] * dv0);
        g_T2h[(base + r1) * 32 + cidx] =
            __floats2half2_rn(acc[t][2] * dv1, acc[t][3] * dv1);
    }
}

// ---------------- layer2 gather + mean-pool fused ---------------------------
__global__ void k_gather_pool(const float* __restrict__ b2,
                              const int* __restrict__ batch) {
    __shared__ __align__(16) float As[64][68];
    __shared__ int sb[64];
    int tid = threadIdx.x;           // 256 threads
    int w = tid >> 5, l = tid & 31;
    int q = l >> 3, li = l & 7;
    int base = blockIdx.x * 64;
    if (tid < 64) sb[tid] = __ldg(&batch[base + tid]);
    float4 bb0 = __ldg(&((const float4*)b2)[li * 2]);
    float4 bb1 = __ldg(&((const float4*)b2)[li * 2 + 1]);
    const uint4* tv = (const uint4*)g_T2h;

    int offp = 0, degp = 0;
    float dvp = 0.f;
    if (l < 8) {
        int nv = base + (w << 3) + l;
        offp = g_off[nv];
        degp = g_deg[nv];
        dvp  = g_dinv[nv];
    }
#pragma unroll
    for (int it = 0; it < 2; it++) {
        int na  = it * 4 + q;
        int v   = base + (w << 3) + na;
        int off = __shfl_sync(0xffffffffu, offp, na);
        int dg  = __shfl_sync(0xffffffffu, degp, na);
        float dv = __shfl_sync(0xffffffffu, dvp, na);
        int d0 = __shfl_sync(0xffffffffu, degp, it * 4);
        int d1 = __shfl_sync(0xffffffffu, degp, it * 4 + 1);
        int d2 = __shfl_sync(0xffffffffu, degp, it * 4 + 2);
        int d3 = __shfl_sync(0xffffffffu, degp, it * 4 + 3);
        int dgmax = max(max(d0, d1), max(d2, d3));

        uint4 se = __ldcg(&tv[v * 8 + li]);     // self loop (L2-only)
        __half2 acc[4];
        acc[0] = *(__half2*)&se.x;
        acc[1] = *(__half2*)&se.y;
        acc[2] = *(__half2*)&se.z;
        acc[3] = *(__half2*)&se.w;
        gather_rows_h(tv, g_csr + off, dg, dgmax, li, acc);

        float2 f0 = __half22float2(acc[0]);
        float2 f1 = __half22float2(acc[1]);
        float2 f2 = __half22float2(acc[2]);
        float2 f3 = __half22float2(acc[3]);
        float o[8];
        o[0] = fmaxf(fmaf(dv, f0.x, bb0.x), 0.f);
        o[1] = fmaxf(fmaf(dv, f0.y, bb0.y), 0.f);
        o[2] = fmaxf(fmaf(dv, f1.x, bb0.z), 0.f);
        o[3] = fmaxf(fmaf(dv, f1.y, bb0.w), 0.f);
        o[4] = fmaxf(fmaf(dv, f2.x, bb1.x), 0.f);
        o[5] = fmaxf(fmaf(dv, f2.y, bb1.y), 0.f);
        o[6] = fmaxf(fmaf(dv, f3.x, bb1.z), 0.f);
        o[7] = fmaxf(fmaf(dv, f3.y, bb1.w), 0.f);
        int row = (w << 3) + na;
        *(float4*)&As[row][li * 8]     = make_float4(o[0], o[1], o[2], o[3]);
        *(float4*)&As[row][li * 8 + 4] = make_float4(o[4], o[5], o[6], o[7]);
    }
    __syncthreads();

    // 64 threads: run-length pool over the 64 smem rows (batch is sorted)
    if (tid < 64) {
        int j = tid;
        int cur = sb[0];
        float acc = 0.f;
        int run = 0;
#pragma unroll 1
        for (int n = 0; n < 64; n++) {
            int gv = sb[n];
            if (gv != cur) {
                atomicAdd(&g_gsum[cur * 64 + j], acc);
                if (j == 0) atomicAdd(&g_cnt[cur], (float)run);
                acc = 0.f;
                run = 0;
                cur = gv;
            }
            acc += As[n][j];
            run++;
        }
        atomicAdd(&g_gsum[cur * 64 + j], acc);
        if (j == 0) atomicAdd(&g_cnt[cur], (float)run);
    }
}

// ---------------- classifier head ------------------------------------------
__global__ void k_final(const float* __restrict__ Wlin,
                        const float* __restrict__ blin,
                        float* __restrict__ out) {
    int g = blockIdx.x * blockDim.x + threadIdx.x;
    if (g >= NG) return;
    float inv = 1.0f / fmaxf(g_cnt[g], 1.0f);
    float a0 = blin[0], a1 = blin[1];
#pragma unroll 8
    for (int j = 0; j < 64; j++) {
        float m = g_gsum[g * 64 + j] * inv;
        a0 = fmaf(m, Wlin[2 * j], a0);
        a1 = fmaf(m, Wlin[2 * j + 1], a1);
    }
    out[2 * g] = a0;
    out[2 * g + 1] = a1;
}

// ---------------- launch ----------------------------------------------------
extern "C" void kernel_launch(void* const* d_in, const int* in_sizes, int n_in,
                              void* d_out, int out_size) {
    const int* x      = (const int*)d_in[0];
    const int* ei     = (const int*)d_in[1];   // [2, NE] row-major
    // d_in[2] = edge_type (unused by GCNConv)
    const int* batch  = (const int*)d_in[3];
    const float* emb  = (const float*)d_in[4];
    const float* W1   = (const float*)d_in[5];
    const float* b1   = (const float*)d_in[6];
    const float* W2   = (const float*)d_in[7];
    const float* b2   = (const float*)d_in[8];
    const float* Wlin = (const float*)d_in[9];
    const float* blin = (const float*)d_in[10];
    float* out = (float*)d_out;

    void* degp = nullptr;
    cudaGetSymbolAddress(&degp, g_deg);
    cudaMemsetAsync(degp, 0, NN * sizeof(int));

    k_prep<<<EMBB + CNTB, 256>>>(emb, W1, W2, ei);   // embW + count + W2->fp16
    k_scan<<<NBLK, 1024>>>();
    k_post<<<FILLB + SEEDB, 256>>>(ei, x);           // csr fill + T1 seed

    k_gather_gemm<<<NN / 64, 256>>>(b1);
    k_gather_pool<<<NN / 64, 256>>>(b2, batch);

    k_final<<<(NG + 255) / 256, 256>>>(Wlin, blin, out);
}